// round 6
// baseline (speedup 1.0000x reference)
#include <cuda_runtime.h>
#include <cuda_fp16.h>
#include <cstdint>

#define BATCH 65536
#define DIN   784
#define DH    320
#define DOUT  10
#define THRESH 0.001f

// GEMM1 tiling
#define BM 128
#define BN 160
#define KC 32              // fp32 K per stage
#define NST 25             // 24 full stages + 1 of K=16
#define BBUF 12800         // 160 rows x 80B (4 chunks of 16B + pad)
#define BSTR 80

__device__ __align__(16) int8_t g_h[(size_t)BATCH * DH];
__device__ __align__(16) __half g_w1h[(size_t)DH * DIN];

__device__ __forceinline__ int tern_i(float v) {
    return v > THRESH ? 1 : (v < -THRESH ? -1 : 0);
}
__device__ __forceinline__ uint32_t h2u(__half2 h) {
    return *reinterpret_cast<uint32_t*>(&h);
}
__device__ __forceinline__ uint32_t smem_u32(const void* p) {
    uint32_t a;
    asm("{ .reg .u64 t; cvta.to.shared.u64 t, %1; cvt.u32.u64 %0, t; }" : "=r"(a) : "l"(p));
    return a;
}
__device__ __forceinline__ void mma16816(float* c, uint32_t a0, uint32_t a1,
                                         uint32_t a2, uint32_t a3,
                                         uint32_t b0, uint32_t b1) {
    asm volatile(
        "mma.sync.aligned.m16n8k16.row.col.f32.f16.f16.f32 "
        "{%0,%1,%2,%3}, {%4,%5,%6,%7}, {%8,%9}, {%0,%1,%2,%3};"
        : "+f"(c[0]), "+f"(c[1]), "+f"(c[2]), "+f"(c[3])
        : "r"(a0), "r"(a1), "r"(a2), "r"(a3), "r"(b0), "r"(b1));
}
__device__ __forceinline__ void ldsm4(uint32_t& r0, uint32_t& r1,
                                      uint32_t& r2, uint32_t& r3, uint32_t a) {
    asm volatile("ldmatrix.sync.aligned.m8n8.x4.shared.b16 {%0,%1,%2,%3}, [%4];"
                 : "=r"(r0), "=r"(r1), "=r"(r2), "=r"(r3) : "r"(a));
}
__device__ __forceinline__ void ldsm2(uint32_t& r0, uint32_t& r1, uint32_t a) {
    asm volatile("ldmatrix.sync.aligned.m8n8.x2.shared.b16 {%0,%1}, [%2];"
                 : "=r"(r0), "=r"(r1) : "r"(a));
}
__device__ __forceinline__ void cpasync16(uint32_t s, const void* g, int pred) {
    asm volatile(
        "{ .reg .pred p; setp.ne.b32 p, %2, 0;\n\t"
        "@p cp.async.cg.shared.global [%0], [%1], 16; }\n"
        :: "r"(s), "l"(g), "r"(pred));
}
#define CP_COMMIT() asm volatile("cp.async.commit_group;" ::: "memory")
#define CP_WAIT0()  asm volatile("cp.async.wait_group 0;" ::: "memory")

// ============================================================================
// prep: ternarize w1 -> fp16 (exact)
// ============================================================================
__global__ void prep_w1(const float* __restrict__ w1) {
    int i = blockIdx.x * 256 + threadIdx.x;
    if (i >= DH * DIN / 2) return;
    float a = w1[2 * i], b = w1[2 * i + 1];
    reinterpret_cast<__half2*>(g_w1h)[i] =
        __floats2half2_rn((float)tern_i(a), (float)tern_i(b));
}

// ============================================================================
// GEMM1: h = tern( x @ tern(w1)^T + b1 ).  HMMA, 2-plane exact fp16 split.
// 512 threads / 16 warps (4M x 4N), warp tile 32x40, K=32/stage.
// A: loaded DIRECTLY from gmem into mma fragment layout (float2 per lane),
//    converted in-register to hi/lo fp16 planes. No A smem at all.
// B: cp.async double-buffered smem, ldmatrix frags, shared by both planes.
// ============================================================================
__global__ __launch_bounds__(512, 1)
void gemm1_hmma(const float* __restrict__ x, const float* __restrict__ b1) {
    __shared__ __align__(16) uint8_t Bs[2][BBUF];
    __shared__ float b1s[BN];

    const int tid  = threadIdx.x;
    const int lane = tid & 31;
    const int wid  = tid >> 5;
    const int wm   = wid >> 2;       // M band 0..3 (32 rows)
    const int wn   = wid & 3;        // N band 0..3 (40 cols)
    const int g    = lane >> 2;
    const int tg   = lane & 3;
    const int m0   = blockIdx.y * BM;
    const int n0   = blockIdx.x * BN;

    const uint32_t bbase = smem_u32(Bs);

    if (tid < BN) b1s[tid] = b1[n0 + tid];

    float acc[2][5][4];
#pragma unroll
    for (int mi = 0; mi < 2; mi++)
#pragma unroll
        for (int ni = 0; ni < 5; ni++)
#pragma unroll
            for (int e = 0; e < 4; e++) acc[mi][ni][e] = 0.0f;

    // B frag smem offsets: two ldsm4 (n 0..31 of band) + one ldsm2 (n 32..39)
    uint32_t bno[2];
#pragma unroll
    for (int j = 0; j < 2; j++)
        bno[j] = (uint32_t)((wn * 40 + j * 16 + (lane & 7) + ((lane >> 4) & 1) * 8) * BSTR
                            + ((lane >> 3) & 1) * 16);
    const uint32_t bno2 = (uint32_t)((wn * 40 + 32 + (lane & 7)) * BSTR
                                     + ((lane >> 3) & 1) * 16);

    // A fragment gmem base: lane covers rows (wm*32 + g [+8] [+16 mi]) at k = tg*2
    const float* abase = x + (size_t)(m0 + wm * 32 + g) * DIN + tg * 2;

    auto ISSUEB = [&](int k0, int buf, int full) {
        const uint32_t bb = bbase + (uint32_t)buf * BBUF;
#pragma unroll
        for (int i = 0; i < 2; i++) {
            int idx = tid + i * 512;
            int row = idx >> 2, ch = idx & 3;
            int ok  = (idx < 640) && (full || ch < 2);
            cpasync16(bb + (uint32_t)(row * BSTR + ch * 16),
                      g_w1h + (size_t)(n0 + (ok ? row : 0)) * DIN + k0 + (ok ? ch : 0) * 8,
                      ok);
        }
        CP_COMMIT();
    };

    // ---- pipeline ----
    ISSUEB(0, 0, 1);

    for (int s = 0; s < NST; s++) {
        const int buf = s & 1;
        CP_WAIT0();
        __syncthreads();
        if (s + 1 < NST) ISSUEB((s + 1) * KC, buf ^ 1, (s + 1 < NST - 1) ? 1 : 0);

        const uint32_t bb = bbase + (uint32_t)buf * BBUF;
        const int nks = (s == NST - 1) ? 1 : 2;
#pragma unroll
        for (int ks = 0; ks < 2; ks++) {
            if (ks >= nks) break;
            // B frags for this k16 (shared by both planes)
            uint32_t bf[10];
#pragma unroll
            for (int j = 0; j < 2; j++)
                ldsm4(bf[4 * j], bf[4 * j + 1], bf[4 * j + 2], bf[4 * j + 3],
                      bb + bno[j] + (uint32_t)(ks * 32));
            ldsm2(bf[8], bf[9], bb + bno2 + (uint32_t)(ks * 32));

            const int kk = s * KC + ks * 16;
#pragma unroll
            for (int mi = 0; mi < 2; mi++) {
                const float* p = abase + (size_t)mi * 16 * DIN + kk;
                float2 u0 = *(const float2*)(p);
                float2 u1 = *(const float2*)(p + 8 * DIN);
                float2 u2 = *(const float2*)(p + 8);
                float2 u3 = *(const float2*)(p + 8 * DIN + 8);

                __half2 h0 = __floats2half2_rn(u0.x, u0.y);
                __half2 h1 = __floats2half2_rn(u1.x, u1.y);
                __half2 h2 = __floats2half2_rn(u2.x, u2.y);
                __half2 h3 = __floats2half2_rn(u3.x, u3.y);
                float2 f0 = __half22float2(h0), f1 = __half22float2(h1);
                float2 f2 = __half22float2(h2), f3 = __half22float2(h3);
                uint32_t l0 = h2u(__floats2half2_rn(u0.x - f0.x, u0.y - f0.y));
                uint32_t l1 = h2u(__floats2half2_rn(u1.x - f1.x, u1.y - f1.y));
                uint32_t l2 = h2u(__floats2half2_rn(u2.x - f2.x, u2.y - f2.y));
                uint32_t l3 = h2u(__floats2half2_rn(u3.x - f3.x, u3.y - f3.y));

#pragma unroll
                for (int ni = 0; ni < 5; ni++)
                    mma16816(acc[mi][ni], h2u(h0), h2u(h1), h2u(h2), h2u(h3),
                             bf[2 * ni], bf[2 * ni + 1]);
#pragma unroll
                for (int ni = 0; ni < 5; ni++)
                    mma16816(acc[mi][ni], l0, l1, l2, l3,
                             bf[2 * ni], bf[2 * ni + 1]);
            }
        }
    }

    // ---- epilogue: +b1, ternarize, int8 store ----
#pragma unroll
    for (int mi = 0; mi < 2; mi++) {
        const int r0 = m0 + wm * 32 + mi * 16 + g;
#pragma unroll
        for (int ni = 0; ni < 5; ni++) {
            const int col = wn * 40 + ni * 8 + tg * 2;
            const float bv0 = b1s[col], bv1 = b1s[col + 1];
            char2 c01, c23;
            c01.x = (signed char)tern_i(acc[mi][ni][0] + bv0);
            c01.y = (signed char)tern_i(acc[mi][ni][1] + bv1);
            c23.x = (signed char)tern_i(acc[mi][ni][2] + bv0);
            c23.y = (signed char)tern_i(acc[mi][ni][3] + bv1);
            *(char2*)(g_h + (size_t)r0 * DH + n0 + col)       = c01;
            *(char2*)(g_h + (size_t)(r0 + 8) * DH + n0 + col) = c23;
        }
    }
}

// ============================================================================
// Head: logits = g_h @ tern(w2)^T + b2 ; log_softmax. 4 threads per row.
// ============================================================================
__global__ __launch_bounds__(256)
void head_kernel(const float* __restrict__ w2,
                 const float* __restrict__ b2,
                 float* __restrict__ out) {
    __shared__ int   q2p[DOUT][DH / 4];
    __shared__ float b2s[DOUT];

    const int tid = threadIdx.x;
    for (int i = tid; i < DOUT * (DH / 4); i += 256) {
        const int o = i / (DH / 4);
        const int w = i % (DH / 4);
        int word = 0;
#pragma unroll
        for (int j = 0; j < 4; j++) {
            int t = tern_i(w2[o * DH + w * 4 + j]);
            word |= (t & 0xFF) << (8 * j);
        }
        q2p[o][w] = word;
    }
    if (tid < DOUT) b2s[tid] = b2[tid];
    __syncthreads();

    const int gidx   = blockIdx.x * 256 + tid;
    const size_t row = (size_t)(gidx >> 2);
    const int q      = gidx & 3;
    const uint4* hp  = (const uint4*)(g_h + row * DH) + q * 5;

    int acc[DOUT];
#pragma unroll
    for (int o = 0; o < DOUT; o++) acc[o] = 0;

#pragma unroll
    for (int c = 0; c < 5; c++) {
        uint4 v = hp[c];
        const int w = q * 20 + c * 4;
#pragma unroll
        for (int o = 0; o < DOUT; o++) {
            acc[o] = __dp4a((int)v.x, q2p[o][w + 0], acc[o]);
            acc[o] = __dp4a((int)v.y, q2p[o][w + 1], acc[o]);
            acc[o] = __dp4a((int)v.z, q2p[o][w + 2], acc[o]);
            acc[o] = __dp4a((int)v.w, q2p[o][w + 3], acc[o]);
        }
    }
#pragma unroll
    for (int o = 0; o < DOUT; o++) {
        acc[o] += __shfl_xor_sync(0xFFFFFFFFu, acc[o], 1);
        acc[o] += __shfl_xor_sync(0xFFFFFFFFu, acc[o], 2);
    }

    if (q == 0) {
        float lg[DOUT];
        float m = -1e30f;
#pragma unroll
        for (int o = 0; o < DOUT; o++) {
            lg[o] = (float)acc[o] + b2s[o];
            m = fmaxf(m, lg[o]);
        }
        float s = 0.0f;
#pragma unroll
        for (int o = 0; o < DOUT; o++) s += expf(lg[o] - m);
        const float lse = m + logf(s);
        float* op = out + row * DOUT;
#pragma unroll
        for (int o = 0; o < DOUT; o++) op[o] = lg[o] - lse;
    }
}

// ============================================================================
extern "C" void kernel_launch(void* const* d_in, const int* in_sizes, int n_in,
                              void* d_out, int out_size) {
    const float* x  = (const float*)d_in[0];
    const float* w1 = (const float*)d_in[1];
    const float* b1 = (const float*)d_in[2];
    const float* w2 = (const float*)d_in[3];
    const float* b2 = (const float*)d_in[4];
    float* out = (float*)d_out;

    prep_w1<<<(DH * DIN / 2 + 255) / 256, 256>>>(w1);
    gemm1_hmma<<<dim3(DH / BN, BATCH / BM), 512>>>(x, b1);
    head_kernel<<<BATCH * 4 / 256, 256>>>(w2, b2, out);
}

// round 7
// speedup vs baseline: 1.3912x; 1.3912x over previous
#include <cuda_runtime.h>
#include <cuda_fp16.h>
#include <cstdint>

#define BATCH 65536
#define DIN   784
#define DH    320
#define DOUT  10
#define THRESH 0.001f

// GEMM1 tiling: CTA 128x80, 8 warps (4M x 2N), 2 CTAs/SM
#define BM 128
#define BN 80
#define KC 32              // fp32 K per stage
#define NST 25             // 24 full stages + 1 of K=16
#define ABUF 16384         // 128 rows x 128B (8 chunks of 16B: 4 hi + 4 lo)
#define BBUF 6400          // 80 rows x 80B
#define BSTR 80

__device__ __align__(16) int8_t g_h[(size_t)BATCH * DH];
__device__ __align__(16) __half g_w1h[(size_t)DH * DIN];

__device__ __forceinline__ int tern_i(float v) {
    return v > THRESH ? 1 : (v < -THRESH ? -1 : 0);
}
__device__ __forceinline__ uint32_t h2u(__half2 h) {
    return *reinterpret_cast<uint32_t*>(&h);
}
__device__ __forceinline__ uint32_t smem_u32(const void* p) {
    uint32_t a;
    asm("{ .reg .u64 t; cvta.to.shared.u64 t, %1; cvt.u32.u64 %0, t; }" : "=r"(a) : "l"(p));
    return a;
}
__device__ __forceinline__ void mma16816(float* c, uint32_t a0, uint32_t a1,
                                         uint32_t a2, uint32_t a3,
                                         uint32_t b0, uint32_t b1) {
    asm volatile(
        "mma.sync.aligned.m16n8k16.row.col.f32.f16.f16.f32 "
        "{%0,%1,%2,%3}, {%4,%5,%6,%7}, {%8,%9}, {%0,%1,%2,%3};"
        : "+f"(c[0]), "+f"(c[1]), "+f"(c[2]), "+f"(c[3])
        : "r"(a0), "r"(a1), "r"(a2), "r"(a3), "r"(b0), "r"(b1));
}
__device__ __forceinline__ void ldsm4(uint32_t& r0, uint32_t& r1,
                                      uint32_t& r2, uint32_t& r3, uint32_t a) {
    asm volatile("ldmatrix.sync.aligned.m8n8.x4.shared.b16 {%0,%1,%2,%3}, [%4];"
                 : "=r"(r0), "=r"(r1), "=r"(r2), "=r"(r3) : "r"(a));
}
__device__ __forceinline__ void ldsm2(uint32_t& r0, uint32_t& r1, uint32_t a) {
    asm volatile("ldmatrix.sync.aligned.m8n8.x2.shared.b16 {%0,%1}, [%2];"
                 : "=r"(r0), "=r"(r1) : "r"(a));
}
__device__ __forceinline__ void sts128(uint32_t a, uint32_t x, uint32_t y,
                                       uint32_t z, uint32_t w) {
    asm volatile("st.shared.v4.b32 [%0], {%1,%2,%3,%4};" :: "r"(a), "r"(x), "r"(y), "r"(z), "r"(w));
}
__device__ __forceinline__ void cpasync16(uint32_t s, const void* g, int pred) {
    asm volatile(
        "{ .reg .pred p; setp.ne.b32 p, %2, 0;\n\t"
        "@p cp.async.cg.shared.global [%0], [%1], 16; }\n"
        :: "r"(s), "l"(g), "r"(pred));
}
#define CP_COMMIT() asm volatile("cp.async.commit_group;" ::: "memory")
#define CP_WAIT0()  asm volatile("cp.async.wait_group 0;" ::: "memory")

// ============================================================================
// prep: ternarize w1 -> fp16 (exact)
// ============================================================================
__global__ void prep_w1(const float* __restrict__ w1) {
    int i = blockIdx.x * 256 + threadIdx.x;
    if (i >= DH * DIN / 2) return;
    float a = w1[2 * i], b = w1[2 * i + 1];
    reinterpret_cast<__half2*>(g_w1h)[i] =
        __floats2half2_rn((float)tern_i(a), (float)tern_i(b));
}

// ============================================================================
// GEMM1: h = tern( x @ tern(w1)^T + b1 ).  HMMA, 2-plane exact fp16 split.
// 256 threads / 8 warps (4M x 2N), warp tile 32x40, K=32/stage, 2 CTAs/SM.
// A smem: row r, chunk c (0..7: 4 hi + 4 lo 16B) at r*128 + ((c^(r&7))<<4)
// B smem: row n, chunk c (0..3) at n*80 + c*16
// ============================================================================
__global__ __launch_bounds__(256, 2)
void gemm1_hmma(const float* __restrict__ x, const float* __restrict__ b1) {
    __shared__ __align__(16) uint8_t As[2][ABUF];
    __shared__ __align__(16) uint8_t Bs[2][BBUF];
    __shared__ float b1s[BN];

    const int tid  = threadIdx.x;
    const int lane = tid & 31;
    const int wid  = tid >> 5;
    const int wm   = wid >> 1;       // M band 0..3 (32 rows)
    const int wn   = wid & 1;        // N band 0..1 (40 cols)
    const int g    = lane >> 2;
    const int tg   = lane & 3;
    const int m0   = blockIdx.y * BM;
    const int n0   = blockIdx.x * BN;

    const uint32_t abase = smem_u32(As);
    const uint32_t bbase = smem_u32(Bs);

    if (tid < BN) b1s[tid] = b1[n0 + tid];

    float acc[2][5][4];
#pragma unroll
    for (int mi = 0; mi < 2; mi++)
#pragma unroll
        for (int ni = 0; ni < 5; ni++)
#pragma unroll
            for (int e = 0; e < 4; e++) acc[mi][ni][e] = 0.0f;

    // ---- frag address precompute ----
    const int cxor = lane & 7;
    const int chi  = lane >> 4;
    uint32_t arow[2];
#pragma unroll
    for (int mi = 0; mi < 2; mi++)
        arow[mi] = (uint32_t)((wm * 32 + mi * 16 + (lane & 15)) * 128);
    uint32_t bno[2];
#pragma unroll
    for (int j = 0; j < 2; j++)
        bno[j] = (uint32_t)((wn * 40 + j * 16 + (lane & 7) + ((lane >> 4) & 1) * 8) * BSTR
                            + ((lane >> 3) & 1) * 16);
    const uint32_t bno2 = (uint32_t)((wn * 40 + 32 + (lane & 7)) * BSTR
                                     + ((lane >> 3) & 1) * 16);

    // ---- A gmem staging: one thread = one (row, k-half of 16) ----
    const int ar = tid >> 1;         // 0..127
    const int hh = tid & 1;          // k 0-15 or 16-31
    const float* xrow = x + (size_t)(m0 + ar) * DIN + hh * 16;
    float4 v0, v1, v2, v3;

    auto LOADA = [&](int k0, int full) {
        if (hh == 0 || full) {
            const float4* p = (const float4*)(xrow + k0);
            v0 = p[0]; v1 = p[1]; v2 = p[2]; v3 = p[3];
        }
    };
    auto ISSUEB = [&](int k0, int buf, int full) {
        const uint32_t bb = bbase + (uint32_t)buf * BBUF;
#pragma unroll
        for (int i = 0; i < 2; i++) {
            int idx = tid + i * 256;
            int row = idx >> 2, ch = idx & 3;
            int ok  = (idx < 320) && (full || ch < 2);
            cpasync16(bb + (uint32_t)(row * BSTR + ch * 16),
                      g_w1h + (size_t)(n0 + (ok ? row : 0)) * DIN + k0 + (ok ? ch : 0) * 8,
                      ok);
        }
        CP_COMMIT();
    };
    auto STOREA = [&](int buf, int full) {
        if (hh == 0 || full) {
            const uint32_t ab = abase + (uint32_t)buf * ABUF + (uint32_t)(ar * 128);
            const int sw = ar & 7;
            __half2 h0 = __floats2half2_rn(v0.x, v0.y), h1 = __floats2half2_rn(v0.z, v0.w);
            __half2 h2 = __floats2half2_rn(v1.x, v1.y), h3 = __floats2half2_rn(v1.z, v1.w);
            __half2 h4 = __floats2half2_rn(v2.x, v2.y), h5 = __floats2half2_rn(v2.z, v2.w);
            __half2 h6 = __floats2half2_rn(v3.x, v3.y), h7 = __floats2half2_rn(v3.z, v3.w);
            float2 f0 = __half22float2(h0), f1 = __half22float2(h1);
            float2 f2 = __half22float2(h2), f3 = __half22float2(h3);
            float2 f4 = __half22float2(h4), f5 = __half22float2(h5);
            float2 f6 = __half22float2(h6), f7 = __half22float2(h7);
            uint32_t l0 = h2u(__floats2half2_rn(v0.x - f0.x, v0.y - f0.y));
            uint32_t l1 = h2u(__floats2half2_rn(v0.z - f1.x, v0.w - f1.y));
            uint32_t l2 = h2u(__floats2half2_rn(v1.x - f2.x, v1.y - f2.y));
            uint32_t l3 = h2u(__floats2half2_rn(v1.z - f3.x, v1.w - f3.y));
            uint32_t l4 = h2u(__floats2half2_rn(v2.x - f4.x, v2.y - f4.y));
            uint32_t l5 = h2u(__floats2half2_rn(v2.z - f5.x, v2.w - f5.y));
            uint32_t l6 = h2u(__floats2half2_rn(v3.x - f6.x, v3.y - f6.y));
            uint32_t l7 = h2u(__floats2half2_rn(v3.z - f7.x, v3.w - f7.y));
            const int c0 = hh * 2, c1 = hh * 2 + 1;
            sts128(ab + (uint32_t)(((c0)     ^ sw) << 4), h2u(h0), h2u(h1), h2u(h2), h2u(h3));
            sts128(ab + (uint32_t)(((c1)     ^ sw) << 4), h2u(h4), h2u(h5), h2u(h6), h2u(h7));
            sts128(ab + (uint32_t)(((c0 + 4) ^ sw) << 4), l0, l1, l2, l3);
            sts128(ab + (uint32_t)(((c1 + 4) ^ sw) << 4), l4, l5, l6, l7);
        }
    };

    auto KSTEP = [&](int buf, int ks) {
        const uint32_t ab = abase + (uint32_t)buf * ABUF;
        const uint32_t bb = bbase + (uint32_t)buf * BBUF;
        uint32_t bf[10];
#pragma unroll
        for (int j = 0; j < 2; j++)
            ldsm4(bf[4 * j], bf[4 * j + 1], bf[4 * j + 2], bf[4 * j + 3],
                  bb + bno[j] + (uint32_t)(ks * 32));
        ldsm2(bf[8], bf[9], bb + bno2 + (uint32_t)(ks * 32));
#pragma unroll
        for (int p = 0; p < 2; p++) {
#pragma unroll
            for (int mi = 0; mi < 2; mi++) {
                uint32_t a0, a1, a2, a3;
                const uint32_t co =
                    (uint32_t)((((p * 4 + ks * 2 + chi) ^ cxor)) << 4);
                ldsm4(a0, a1, a2, a3, ab + arow[mi] + co);
#pragma unroll
                for (int ni = 0; ni < 5; ni++)
                    mma16816(acc[mi][ni], a0, a1, a2, a3, bf[2 * ni], bf[2 * ni + 1]);
            }
        }
    };

    // ---- pipeline ----
    ISSUEB(0, 0, 1);
    LOADA(0, 1);
    STOREA(0, 1);
    CP_WAIT0();
    __syncthreads();

    for (int kt = 0; kt < NST - 1; kt++) {
        const int buf  = kt & 1;
        const int full = (kt + 1 < NST - 1) ? 1 : 0;
        ISSUEB((kt + 1) * KC, buf ^ 1, full);
        LOADA((kt + 1) * KC, full);
        KSTEP(buf, 0);
        KSTEP(buf, 1);
        STOREA(buf ^ 1, full);
        CP_WAIT0();
        __syncthreads();
    }
    // final stage (K=16), buf = (NST-1)&1 = 0
    KSTEP(0, 0);

    // ---- epilogue: +b1, ternarize, int8 store ----
#pragma unroll
    for (int mi = 0; mi < 2; mi++) {
        const int r0 = m0 + wm * 32 + mi * 16 + g;
#pragma unroll
        for (int ni = 0; ni < 5; ni++) {
            const int col = wn * 40 + ni * 8 + tg * 2;
            const float bv0 = b1s[col], bv1 = b1s[col + 1];
            char2 c01, c23;
            c01.x = (signed char)tern_i(acc[mi][ni][0] + bv0);
            c01.y = (signed char)tern_i(acc[mi][ni][1] + bv1);
            c23.x = (signed char)tern_i(acc[mi][ni][2] + bv0);
            c23.y = (signed char)tern_i(acc[mi][ni][3] + bv1);
            *(char2*)(g_h + (size_t)r0 * DH + n0 + col)       = c01;
            *(char2*)(g_h + (size_t)(r0 + 8) * DH + n0 + col) = c23;
        }
    }
}

// ============================================================================
// Head: logits = g_h @ tern(w2)^T + b2 ; log_softmax. 4 threads per row.
// ============================================================================
__global__ __launch_bounds__(256)
void head_kernel(const float* __restrict__ w2,
                 const float* __restrict__ b2,
                 float* __restrict__ out) {
    __shared__ int   q2p[DOUT][DH / 4];
    __shared__ float b2s[DOUT];

    const int tid = threadIdx.x;
    for (int i = tid; i < DOUT * (DH / 4); i += 256) {
        const int o = i / (DH / 4);
        const int w = i % (DH / 4);
        int word = 0;
#pragma unroll
        for (int j = 0; j < 4; j++) {
            int t = tern_i(w2[o * DH + w * 4 + j]);
            word |= (t & 0xFF) << (8 * j);
        }
        q2p[o][w] = word;
    }
    if (tid < DOUT) b2s[tid] = b2[tid];
    __syncthreads();

    const int gidx   = blockIdx.x * 256 + tid;
    const size_t row = (size_t)(gidx >> 2);
    const int q      = gidx & 3;
    const uint4* hp  = (const uint4*)(g_h + row * DH) + q * 5;

    int acc[DOUT];
#pragma unroll
    for (int o = 0; o < DOUT; o++) acc[o] = 0;

#pragma unroll
    for (int c = 0; c < 5; c++) {
        uint4 v = hp[c];
        const int w = q * 20 + c * 4;
#pragma unroll
        for (int o = 0; o < DOUT; o++) {
            acc[o] = __dp4a((int)v.x, q2p[o][w + 0], acc[o]);
            acc[o] = __dp4a((int)v.y, q2p[o][w + 1], acc[o]);
            acc[o] = __dp4a((int)v.z, q2p[o][w + 2], acc[o]);
            acc[o] = __dp4a((int)v.w, q2p[o][w + 3], acc[o]);
        }
    }
#pragma unroll
    for (int o = 0; o < DOUT; o++) {
        acc[o] += __shfl_xor_sync(0xFFFFFFFFu, acc[o], 1);
        acc[o] += __shfl_xor_sync(0xFFFFFFFFu, acc[o], 2);
    }

    if (q == 0) {
        float lg[DOUT];
        float m = -1e30f;
#pragma unroll
        for (int o = 0; o < DOUT; o++) {
            lg[o] = (float)acc[o] + b2s[o];
            m = fmaxf(m, lg[o]);
        }
        float s = 0.0f;
#pragma unroll
        for (int o = 0; o < DOUT; o++) s += expf(lg[o] - m);
        const float lse = m + logf(s);
        float* op = out + row * DOUT;
#pragma unroll
        for (int o = 0; o < DOUT; o++) op[o] = lg[o] - lse;
    }
}

// ============================================================================
extern "C" void kernel_launch(void* const* d_in, const int* in_sizes, int n_in,
                              void* d_out, int out_size) {
    const float* x  = (const float*)d_in[0];
    const float* w1 = (const float*)d_in[1];
    const float* b1 = (const float*)d_in[2];
    const float* w2 = (const float*)d_in[3];
    const float* b2 = (const float*)d_in[4];
    float* out = (float*)d_out;

    prep_w1<<<(DH * DIN / 2 + 255) / 256, 256>>>(w1);
    gemm1_hmma<<<dim3(DH / BN, BATCH / BM), 256>>>(x, b1);
    head_kernel<<<BATCH * 4 / 256, 256>>>(w2, b2, out);
}

// round 8
// speedup vs baseline: 1.7323x; 1.2451x over previous
#include <cuda_runtime.h>
#include <cuda_fp16.h>
#include <cstdint>

#define BATCH 65536
#define DIN   784
#define DH    320
#define DOUT  10
#define THRESH 0.001f
#define MARGIN 0.035f
#define CAP    (1 << 20)

// GEMM1 tiling: CTA 128x160, 16 warps (4M x 4N), K=32/stage, single fp16 plane
#define BM 128
#define BN 160
#define KC 32
#define NST 25             // 24 full stages + 1 of K=16
#define ABUF 8192          // 128 rows x 64B (4 chunks of 16B, swizzled)
#define BBUF 12800         // 160 rows x 80B
#define BSTR 80

__device__ __align__(16) int8_t   g_h[(size_t)BATCH * DH];
__device__ __align__(16) __half   g_w1h[(size_t)DH * DIN];
__device__ __align__(16) uint32_t g_list[CAP];
__device__ int g_cnt;

__device__ __forceinline__ int tern_i(float v) {
    return v > THRESH ? 1 : (v < -THRESH ? -1 : 0);
}
__device__ __forceinline__ uint32_t h2u(__half2 h) {
    return *reinterpret_cast<uint32_t*>(&h);
}
__device__ __forceinline__ uint32_t smem_u32(const void* p) {
    uint32_t a;
    asm("{ .reg .u64 t; cvta.to.shared.u64 t, %1; cvt.u32.u64 %0, t; }" : "=r"(a) : "l"(p));
    return a;
}
__device__ __forceinline__ void mma16816(float* c, uint32_t a0, uint32_t a1,
                                         uint32_t a2, uint32_t a3,
                                         uint32_t b0, uint32_t b1) {
    asm volatile(
        "mma.sync.aligned.m16n8k16.row.col.f32.f16.f16.f32 "
        "{%0,%1,%2,%3}, {%4,%5,%6,%7}, {%8,%9}, {%0,%1,%2,%3};"
        : "+f"(c[0]), "+f"(c[1]), "+f"(c[2]), "+f"(c[3])
        : "r"(a0), "r"(a1), "r"(a2), "r"(a3), "r"(b0), "r"(b1));
}
__device__ __forceinline__ void ldsm4(uint32_t& r0, uint32_t& r1,
                                      uint32_t& r2, uint32_t& r3, uint32_t a) {
    asm volatile("ldmatrix.sync.aligned.m8n8.x4.shared.b16 {%0,%1,%2,%3}, [%4];"
                 : "=r"(r0), "=r"(r1), "=r"(r2), "=r"(r3) : "r"(a));
}
__device__ __forceinline__ void ldsm2(uint32_t& r0, uint32_t& r1, uint32_t a) {
    asm volatile("ldmatrix.sync.aligned.m8n8.x2.shared.b16 {%0,%1}, [%2];"
                 : "=r"(r0), "=r"(r1) : "r"(a));
}
__device__ __forceinline__ void sts128(uint32_t a, uint32_t x, uint32_t y,
                                       uint32_t z, uint32_t w) {
    asm volatile("st.shared.v4.b32 [%0], {%1,%2,%3,%4};" :: "r"(a), "r"(x), "r"(y), "r"(z), "r"(w));
}
__device__ __forceinline__ void cpasync16(uint32_t s, const void* g, int pred) {
    asm volatile(
        "{ .reg .pred p; setp.ne.b32 p, %2, 0;\n\t"
        "@p cp.async.cg.shared.global [%0], [%1], 16; }\n"
        :: "r"(s), "l"(g), "r"(pred));
}
#define CP_COMMIT() asm volatile("cp.async.commit_group;" ::: "memory")
#define CP_WAIT0()  asm volatile("cp.async.wait_group 0;" ::: "memory")

// ============================================================================
__global__ void prep_w1(const float* __restrict__ w1) {
    int i = blockIdx.x * 256 + threadIdx.x;
    if (i >= DH * DIN / 2) return;
    float a = w1[2 * i], b = w1[2 * i + 1];
    reinterpret_cast<__half2*>(g_w1h)[i] =
        __floats2half2_rn((float)tern_i(a), (float)tern_i(b));
}
__global__ void zero_cnt_kernel() { g_cnt = 0; }

// ============================================================================
// GEMM1 (hi plane only): h~ = x_hi @ tern(w1)^T; provisional ternarize;
// flag |(|h~+b1|)-T| < MARGIN into g_list for exact fp32 recompute.
// A smem: row r, chunk c(0..3) at r*64 + ((c ^ ((r>>1)&3))<<4)
// ============================================================================
__global__ __launch_bounds__(512, 1)
void gemm1_hmma(const float* __restrict__ x, const float* __restrict__ b1) {
    __shared__ __align__(16) uint8_t As[2][ABUF];
    __shared__ __align__(16) uint8_t Bs[2][BBUF];
    __shared__ float b1s[BN];

    const int tid  = threadIdx.x;
    const int lane = tid & 31;
    const int wid  = tid >> 5;
    const int wm   = wid >> 2;       // M band 0..3
    const int wn   = wid & 3;        // N band 0..3
    const int g    = lane >> 2;
    const int tg   = lane & 3;
    const int m0   = blockIdx.y * BM;
    const int n0   = blockIdx.x * BN;

    const uint32_t abase = smem_u32(As);
    const uint32_t bbase = smem_u32(Bs);

    if (tid < BN) b1s[tid] = b1[n0 + tid];

    float acc[2][5][4];
#pragma unroll
    for (int mi = 0; mi < 2; mi++)
#pragma unroll
        for (int ni = 0; ni < 5; ni++)
#pragma unroll
            for (int e = 0; e < 4; e++) acc[mi][ni][e] = 0.0f;

    // ---- frag address precompute ----
    const int chi = lane >> 4;       // chunk low bit per half-warp
    uint32_t arow[2];
    int sxor[2];
#pragma unroll
    for (int mi = 0; mi < 2; mi++) {
        const int r = wm * 32 + mi * 16 + (lane & 15);
        arow[mi] = (uint32_t)(r * 64);
        sxor[mi] = (r >> 1) & 3;
    }
    uint32_t bno[2];
#pragma unroll
    for (int j = 0; j < 2; j++)
        bno[j] = (uint32_t)((wn * 40 + j * 16 + (lane & 7) + ((lane >> 4) & 1) * 8) * BSTR
                            + ((lane >> 3) & 1) * 16);
    const uint32_t bno2 = (uint32_t)((wn * 40 + 32 + (lane & 7)) * BSTR
                                     + ((lane >> 3) & 1) * 16);

    // ---- A gmem staging: one thread = (row, 8-fp32 k-group) ----
    const int ar = tid >> 2;         // 0..127
    const int aq = tid & 3;          // k: aq*8 .. aq*8+7
    const float* xrow = x + (size_t)(m0 + ar) * DIN + aq * 8;
    float4 v0, v1;

    auto LOADA = [&](int k0, int full) {
        if (aq < 2 || full) {
            const float4* p = (const float4*)(xrow + k0);
            v0 = p[0]; v1 = p[1];
        }
    };
    auto ISSUEB = [&](int k0, int buf, int full) {
        const uint32_t bb = bbase + (uint32_t)buf * BBUF;
#pragma unroll
        for (int i = 0; i < 2; i++) {
            int idx = tid + i * 512;
            int row = idx >> 2, ch = idx & 3;
            int ok  = (idx < 640) && (full || ch < 2);
            cpasync16(bb + (uint32_t)(row * BSTR + ch * 16),
                      g_w1h + (size_t)(n0 + (ok ? row : 0)) * DIN + k0 + (ok ? ch : 0) * 8,
                      ok);
        }
        CP_COMMIT();
    };
    auto STOREA = [&](int buf, int full) {
        if (aq < 2 || full) {
            const uint32_t ab = abase + (uint32_t)buf * ABUF + (uint32_t)(ar * 64);
            const int sw = (ar >> 1) & 3;
            __half2 h0 = __floats2half2_rn(v0.x, v0.y);
            __half2 h1 = __floats2half2_rn(v0.z, v0.w);
            __half2 h2 = __floats2half2_rn(v1.x, v1.y);
            __half2 h3 = __floats2half2_rn(v1.z, v1.w);
            sts128(ab + (uint32_t)((aq ^ sw) << 4), h2u(h0), h2u(h1), h2u(h2), h2u(h3));
        }
    };

    auto KSTEP = [&](int buf, int ks) {
        const uint32_t ab = abase + (uint32_t)buf * ABUF;
        const uint32_t bb = bbase + (uint32_t)buf * BBUF;
        uint32_t bf[10];
#pragma unroll
        for (int j = 0; j < 2; j++)
            ldsm4(bf[4 * j], bf[4 * j + 1], bf[4 * j + 2], bf[4 * j + 3],
                  bb + bno[j] + (uint32_t)(ks * 32));
        ldsm2(bf[8], bf[9], bb + bno2 + (uint32_t)(ks * 32));
#pragma unroll
        for (int mi = 0; mi < 2; mi++) {
            uint32_t a0, a1, a2, a3;
            const uint32_t co = (uint32_t)(((ks * 2 + chi) ^ sxor[mi]) << 4);
            ldsm4(a0, a1, a2, a3, ab + arow[mi] + co);
#pragma unroll
            for (int ni = 0; ni < 5; ni++)
                mma16816(acc[mi][ni], a0, a1, a2, a3, bf[2 * ni], bf[2 * ni + 1]);
        }
    };

    // ---- pipeline ----
    ISSUEB(0, 0, 1);
    LOADA(0, 1);
    STOREA(0, 1);
    CP_WAIT0();
    __syncthreads();

    for (int kt = 0; kt < NST - 1; kt++) {
        const int buf  = kt & 1;
        const int full = (kt + 1 < NST - 1) ? 1 : 0;
        ISSUEB((kt + 1) * KC, buf ^ 1, full);
        LOADA((kt + 1) * KC, full);
        KSTEP(buf, 0);
        KSTEP(buf, 1);
        STOREA(buf ^ 1, full);
        CP_WAIT0();
        __syncthreads();
    }
    KSTEP(0, 0);   // final stage, K=16, buf 0

    // ---- epilogue: +b1, provisional ternarize, flag near-threshold ----
    int cnt = 0;
#pragma unroll
    for (int mi = 0; mi < 2; mi++) {
        const int r0 = m0 + wm * 32 + mi * 16 + g;
#pragma unroll
        for (int ni = 0; ni < 5; ni++) {
            const int col = wn * 40 + ni * 8 + tg * 2;
            const float bv0 = b1s[col], bv1 = b1s[col + 1];
            float w0 = acc[mi][ni][0] + bv0, w1v = acc[mi][ni][1] + bv1;
            float w2v = acc[mi][ni][2] + bv0, w3 = acc[mi][ni][3] + bv1;
            char2 c01, c23;
            c01.x = (signed char)tern_i(w0); c01.y = (signed char)tern_i(w1v);
            c23.x = (signed char)tern_i(w2v); c23.y = (signed char)tern_i(w3);
            *(char2*)(g_h + (size_t)r0 * DH + n0 + col)       = c01;
            *(char2*)(g_h + (size_t)(r0 + 8) * DH + n0 + col) = c23;
            cnt += (fabsf(fabsf(w0) - THRESH) < MARGIN);
            cnt += (fabsf(fabsf(w1v) - THRESH) < MARGIN);
            cnt += (fabsf(fabsf(w2v) - THRESH) < MARGIN);
            cnt += (fabsf(fabsf(w3) - THRESH) < MARGIN);
        }
    }
    // warp scan + one atomic per warp
    int incl = cnt;
#pragma unroll
    for (int d = 1; d < 32; d <<= 1) {
        int t = __shfl_up_sync(0xFFFFFFFFu, incl, d);
        if (lane >= d) incl += t;
    }
    const int excl = incl - cnt;
    const int tot  = __shfl_sync(0xFFFFFFFFu, incl, 31);
    if (tot) {
        int base = 0;
        if (lane == 0) base = atomicAdd(&g_cnt, tot);
        base = __shfl_sync(0xFFFFFFFFu, base, 0);
        int p = base + excl;
#pragma unroll
        for (int mi = 0; mi < 2; mi++) {
            const int r0 = m0 + wm * 32 + mi * 16 + g;
#pragma unroll
            for (int ni = 0; ni < 5; ni++) {
                const int col = wn * 40 + ni * 8 + tg * 2;
                const float bv0 = b1s[col], bv1 = b1s[col + 1];
                const float vv[4] = { acc[mi][ni][0] + bv0, acc[mi][ni][1] + bv1,
                                      acc[mi][ni][2] + bv0, acc[mi][ni][3] + bv1 };
                const int rr[4] = { r0, r0, r0 + 8, r0 + 8 };
                const int cc[4] = { col, col + 1, col, col + 1 };
#pragma unroll
                for (int e = 0; e < 4; e++) {
                    if (fabsf(fabsf(vv[e]) - THRESH) < MARGIN) {
                        if (p < CAP)
                            g_list[p] = ((uint32_t)rr[e] << 9) | (uint32_t)(n0 + cc[e]);
                        p++;
                    }
                }
            }
        }
    }
}

// ============================================================================
// Correction: exact fp32 recompute of flagged h elements. One warp per entry.
// ============================================================================
__global__ __launch_bounds__(256)
void corr_kernel(const float* __restrict__ x, const float* __restrict__ b1) {
    const int lane = threadIdx.x & 31;
    const int wg   = (blockIdx.x * 256 + threadIdx.x) >> 5;
    const int nw   = (gridDim.x * 256) >> 5;
    int total = g_cnt;
    if (total > CAP) total = CAP;

    for (int e = wg; e < total; e += nw) {
        const uint32_t u = g_list[e];
        const int row = (int)(u >> 9);
        const int n   = (int)(u & 511);
        const float* xr = x + (size_t)row * DIN;
        const __half* wr = g_w1h + (size_t)n * DIN;
        float s = 0.0f;
        for (int k = lane; k < DIN; k += 32)
            s += xr[k] * __half2float(wr[k]);
#pragma unroll
        for (int d = 16; d; d >>= 1)
            s += __shfl_xor_sync(0xFFFFFFFFu, s, d);
        if (lane == 0)
            g_h[(size_t)row * DH + n] = (int8_t)tern_i(s + b1[n]);
    }
}

// ============================================================================
// Head: logits = g_h @ tern(w2)^T + b2 ; log_softmax. 4 threads per row.
// ============================================================================
__global__ __launch_bounds__(256)
void head_kernel(const float* __restrict__ w2,
                 const float* __restrict__ b2,
                 float* __restrict__ out) {
    __shared__ int   q2p[DOUT][DH / 4];
    __shared__ float b2s[DOUT];

    const int tid = threadIdx.x;
    for (int i = tid; i < DOUT * (DH / 4); i += 256) {
        const int o = i / (DH / 4);
        const int w = i % (DH / 4);
        int word = 0;
#pragma unroll
        for (int j = 0; j < 4; j++) {
            int t = tern_i(w2[o * DH + w * 4 + j]);
            word |= (t & 0xFF) << (8 * j);
        }
        q2p[o][w] = word;
    }
    if (tid < DOUT) b2s[tid] = b2[tid];
    __syncthreads();

    const int gidx   = blockIdx.x * 256 + tid;
    const size_t row = (size_t)(gidx >> 2);
    const int q      = gidx & 3;
    const uint4* hp  = (const uint4*)(g_h + row * DH) + q * 5;

    int acc[DOUT];
#pragma unroll
    for (int o = 0; o < DOUT; o++) acc[o] = 0;

#pragma unroll
    for (int c = 0; c < 5; c++) {
        uint4 v = hp[c];
        const int w = q * 20 + c * 4;
#pragma unroll
        for (int o = 0; o < DOUT; o++) {
            acc[o] = __dp4a((int)v.x, q2p[o][w + 0], acc[o]);
            acc[o] = __dp4a((int)v.y, q2p[o][w + 1], acc[o]);
            acc[o] = __dp4a((int)v.z, q2p[o][w + 2], acc[o]);
            acc[o] = __dp4a((int)v.w, q2p[o][w + 3], acc[o]);
        }
    }
#pragma unroll
    for (int o = 0; o < DOUT; o++) {
        acc[o] += __shfl_xor_sync(0xFFFFFFFFu, acc[o], 1);
        acc[o] += __shfl_xor_sync(0xFFFFFFFFu, acc[o], 2);
    }

    if (q == 0) {
        float lg[DOUT];
        float m = -1e30f;
#pragma unroll
        for (int o = 0; o < DOUT; o++) {
            lg[o] = (float)acc[o] + b2s[o];
            m = fmaxf(m, lg[o]);
        }
        float s = 0.0f;
#pragma unroll
        for (int o = 0; o < DOUT; o++) s += expf(lg[o] - m);
        const float lse = m + logf(s);
        float* op = out + row * DOUT;
#pragma unroll
        for (int o = 0; o < DOUT; o++) op[o] = lg[o] - lse;
    }
}

// ============================================================================
extern "C" void kernel_launch(void* const* d_in, const int* in_sizes, int n_in,
                              void* d_out, int out_size) {
    const float* x  = (const float*)d_in[0];
    const float* w1 = (const float*)d_in[1];
    const float* b1 = (const float*)d_in[2];
    const float* w2 = (const float*)d_in[3];
    const float* b2 = (const float*)d_in[4];
    float* out = (float*)d_out;

    prep_w1<<<(DH * DIN / 2 + 255) / 256, 256>>>(w1);
    zero_cnt_kernel<<<1, 1>>>();
    gemm1_hmma<<<dim3(DH / BN, BATCH / BM), 512>>>(x, b1);
    corr_kernel<<<512, 256>>>(x, b1);
    head_kernel<<<BATCH * 4 / 256, 256>>>(w2, b2, out);
}

// round 9
// speedup vs baseline: 1.8134x; 1.0468x over previous
#include <cuda_runtime.h>
#include <cuda_fp16.h>
#include <cstdint>

#define BATCH 65536
#define DIN   784
#define DH    320
#define DOUT  10
#define THRESH 0.001f
#define MARGIN 0.035f
#define CAP    (1 << 20)

// GEMM1 tiling: CTA 128x160, 16 warps (4M x 4N), K=64/stage, single fp16 plane
#define BM 128
#define BN 160
#define KC 64
#define NFULL 12           // 12 x 64 + 1 x 16 = 784
#define ABUF 16384         // 128 rows x 128B (8 chunks of 16B, swizzled c^(r&7))
#define BSTR 144           // 160 rows x (128B data + 16B pad)
#define BBUF (160*BSTR)    // 23040
#define SMEM_DYN (2*ABUF + 2*BBUF + BN*4)   // 79488

__device__ __align__(16) int8_t   g_h[(size_t)BATCH * DH];
__device__ __align__(16) __half   g_w1h[(size_t)DH * DIN];
__device__ __align__(16) uint32_t g_list[CAP];
__device__ int g_cnt;

__device__ __forceinline__ int tern_i(float v) {
    return v > THRESH ? 1 : (v < -THRESH ? -1 : 0);
}
__device__ __forceinline__ uint32_t h2u(__half2 h) {
    return *reinterpret_cast<uint32_t*>(&h);
}
__device__ __forceinline__ uint32_t smem_u32(const void* p) {
    uint32_t a;
    asm("{ .reg .u64 t; cvta.to.shared.u64 t, %1; cvt.u32.u64 %0, t; }" : "=r"(a) : "l"(p));
    return a;
}
__device__ __forceinline__ void mma16816(float* c, uint32_t a0, uint32_t a1,
                                         uint32_t a2, uint32_t a3,
                                         uint32_t b0, uint32_t b1) {
    asm volatile(
        "mma.sync.aligned.m16n8k16.row.col.f32.f16.f16.f32 "
        "{%0,%1,%2,%3}, {%4,%5,%6,%7}, {%8,%9}, {%0,%1,%2,%3};"
        : "+f"(c[0]), "+f"(c[1]), "+f"(c[2]), "+f"(c[3])
        : "r"(a0), "r"(a1), "r"(a2), "r"(a3), "r"(b0), "r"(b1));
}
__device__ __forceinline__ void ldsm4(uint32_t& r0, uint32_t& r1,
                                      uint32_t& r2, uint32_t& r3, uint32_t a) {
    asm volatile("ldmatrix.sync.aligned.m8n8.x4.shared.b16 {%0,%1,%2,%3}, [%4];"
                 : "=r"(r0), "=r"(r1), "=r"(r2), "=r"(r3) : "r"(a));
}
__device__ __forceinline__ void ldsm2(uint32_t& r0, uint32_t& r1, uint32_t a) {
    asm volatile("ldmatrix.sync.aligned.m8n8.x2.shared.b16 {%0,%1}, [%2];"
                 : "=r"(r0), "=r"(r1) : "r"(a));
}
__device__ __forceinline__ void sts128(uint32_t a, uint32_t x, uint32_t y,
                                       uint32_t z, uint32_t w) {
    asm volatile("st.shared.v4.b32 [%0], {%1,%2,%3,%4};" :: "r"(a), "r"(x), "r"(y), "r"(z), "r"(w));
}
__device__ __forceinline__ void cpasync16(uint32_t s, const void* g, int pred) {
    asm volatile(
        "{ .reg .pred p; setp.ne.b32 p, %2, 0;\n\t"
        "@p cp.async.cg.shared.global [%0], [%1], 16; }\n"
        :: "r"(s), "l"(g), "r"(pred));
}
#define CP_COMMIT() asm volatile("cp.async.commit_group;" ::: "memory")
#define CP_WAIT0()  asm volatile("cp.async.wait_group 0;" ::: "memory")

// ============================================================================
__global__ void prep_w1(const float* __restrict__ w1) {
    if (blockIdx.x == 0 && threadIdx.x == 0) g_cnt = 0;
    int i = blockIdx.x * 256 + threadIdx.x;
    if (i >= DH * DIN / 2) return;
    float a = w1[2 * i], b = w1[2 * i + 1];
    reinterpret_cast<__half2*>(g_w1h)[i] =
        __floats2half2_rn((float)tern_i(a), (float)tern_i(b));
}

// ============================================================================
// GEMM1 (hi plane): provisional ternarize + flag near-threshold elements.
// A smem: row r, chunk c(0..7, 16B) at r*128 + ((c ^ (r&7))<<4)
// B smem: row n stride 144B, chunk c(0..7) at n*144 + c*16
// ============================================================================
__global__ __launch_bounds__(512, 1)
void gemm1_hmma(const float* __restrict__ x, const float* __restrict__ b1) {
    extern __shared__ __align__(16) uint8_t sm[];
    const uint32_t abase = smem_u32(sm);
    const uint32_t bbase = abase + 2 * ABUF;
    float* b1s = (float*)(sm + 2 * ABUF + 2 * BBUF);

    const int tid  = threadIdx.x;
    const int lane = tid & 31;
    const int wid  = tid >> 5;
    const int wm   = wid >> 2;       // M band 0..3
    const int wn   = wid & 3;        // N band 0..3
    const int g    = lane >> 2;
    const int tg   = lane & 3;
    const int m0   = blockIdx.y * BM;
    const int n0   = blockIdx.x * BN;

    if (tid < BN) b1s[tid] = b1[n0 + tid];

    float acc[2][5][4];
#pragma unroll
    for (int mi = 0; mi < 2; mi++)
#pragma unroll
        for (int ni = 0; ni < 5; ni++)
#pragma unroll
            for (int e = 0; e < 4; e++) acc[mi][ni][e] = 0.0f;

    // ---- frag address precompute ----
    const int cxor = lane & 7;       // == r&7 for ldsm source rows
    const int chi  = lane >> 4;      // chunk parity per half-warp
    uint32_t arow[2];
#pragma unroll
    for (int mi = 0; mi < 2; mi++)
        arow[mi] = (uint32_t)((wm * 32 + mi * 16 + (lane & 15)) * 128);
    uint32_t bno[2];
#pragma unroll
    for (int j = 0; j < 2; j++)
        bno[j] = (uint32_t)((wn * 40 + j * 16 + (lane & 7) + ((lane >> 4) & 1) * 8) * BSTR
                            + ((lane >> 3) & 1) * 16);
    const uint32_t bno2 = (uint32_t)((wn * 40 + 32 + (lane & 7)) * BSTR
                                     + ((lane >> 3) & 1) * 16);

    // ---- A gmem staging: thread = (row ar, 16-fp32 k-quarter aq) ----
    const int ar = tid >> 2;         // 0..127
    const int aq = tid & 3;          // k: aq*16 .. aq*16+15
    const float* xrow = x + (size_t)(m0 + ar) * DIN + aq * 16;
    float4 v0, v1, v2, v3;

    auto LOADA = [&](int k0, int full) {
        if (aq == 0 || full) {
            const float4* p = (const float4*)(xrow + k0);
            v0 = p[0]; v1 = p[1]; v2 = p[2]; v3 = p[3];
        }
    };
    auto ISSUEB = [&](int k0, int buf, int full) {
        const uint32_t bb = bbase + (uint32_t)buf * BBUF;
#pragma unroll
        for (int i = 0; i < 3; i++) {
            int idx = tid + i * 512;
            int row = idx >> 3, ch = idx & 7;
            int ok  = (idx < 1280) && (full || ch < 2);
            cpasync16(bb + (uint32_t)(row * BSTR + ch * 16),
                      g_w1h + (size_t)(n0 + (ok ? row : 0)) * DIN + k0 + (ok ? ch : 0) * 8,
                      ok);
        }
        CP_COMMIT();
    };
    auto STOREA = [&](int buf, int full) {
        if (aq == 0 || full) {
            const uint32_t ab = abase + (uint32_t)buf * ABUF + (uint32_t)(ar * 128);
            const int sw = ar & 7;
            __half2 h0 = __floats2half2_rn(v0.x, v0.y), h1 = __floats2half2_rn(v0.z, v0.w);
            __half2 h2 = __floats2half2_rn(v1.x, v1.y), h3 = __floats2half2_rn(v1.z, v1.w);
            __half2 h4 = __floats2half2_rn(v2.x, v2.y), h5 = __floats2half2_rn(v2.z, v2.w);
            __half2 h6 = __floats2half2_rn(v3.x, v3.y), h7 = __floats2half2_rn(v3.z, v3.w);
            const int c0 = aq * 2, c1 = aq * 2 + 1;
            sts128(ab + (uint32_t)((c0 ^ sw) << 4), h2u(h0), h2u(h1), h2u(h2), h2u(h3));
            sts128(ab + (uint32_t)((c1 ^ sw) << 4), h2u(h4), h2u(h5), h2u(h6), h2u(h7));
        }
    };

    auto KSTEP = [&](int buf, int ks) {
        const uint32_t ab = abase + (uint32_t)buf * ABUF;
        const uint32_t bb = bbase + (uint32_t)buf * BBUF;
        uint32_t bf[10];
#pragma unroll
        for (int j = 0; j < 2; j++)
            ldsm4(bf[4 * j], bf[4 * j + 1], bf[4 * j + 2], bf[4 * j + 3],
                  bb + bno[j] + (uint32_t)(ks * 32));
        ldsm2(bf[8], bf[9], bb + bno2 + (uint32_t)(ks * 32));
#pragma unroll
        for (int mi = 0; mi < 2; mi++) {
            uint32_t a0, a1, a2, a3;
            const uint32_t co = (uint32_t)(((ks * 2 + chi) ^ cxor) << 4);
            ldsm4(a0, a1, a2, a3, ab + arow[mi] + co);
#pragma unroll
            for (int ni = 0; ni < 5; ni++)
                mma16816(acc[mi][ni], a0, a1, a2, a3, bf[2 * ni], bf[2 * ni + 1]);
        }
    };

    // ---- pipeline ----
    ISSUEB(0, 0, 1);
    LOADA(0, 1);
    STOREA(0, 1);
    CP_WAIT0();
    __syncthreads();

    for (int kt = 0; kt < NFULL; kt++) {
        const int buf  = kt & 1;
        const int full = (kt + 1 < NFULL) ? 1 : 0;
        ISSUEB((kt + 1) * KC, buf ^ 1, full);
        LOADA((kt + 1) * KC, full);
        KSTEP(buf, 0);
        KSTEP(buf, 1);
        KSTEP(buf, 2);
        KSTEP(buf, 3);
        STOREA(buf ^ 1, full);
        CP_WAIT0();
        __syncthreads();
    }
    KSTEP(0, 0);   // tail stage: K=16, buf 0

    // ---- epilogue: +b1, provisional ternarize, flag near-threshold ----
    int cnt = 0;
#pragma unroll
    for (int mi = 0; mi < 2; mi++) {
        const int r0 = m0 + wm * 32 + mi * 16 + g;
#pragma unroll
        for (int ni = 0; ni < 5; ni++) {
            const int col = wn * 40 + ni * 8 + tg * 2;
            const float bv0 = b1s[col], bv1 = b1s[col + 1];
            float w0 = acc[mi][ni][0] + bv0, w1v = acc[mi][ni][1] + bv1;
            float w2v = acc[mi][ni][2] + bv0, w3 = acc[mi][ni][3] + bv1;
            char2 c01, c23;
            c01.x = (signed char)tern_i(w0); c01.y = (signed char)tern_i(w1v);
            c23.x = (signed char)tern_i(w2v); c23.y = (signed char)tern_i(w3);
            *(char2*)(g_h + (size_t)r0 * DH + n0 + col)       = c01;
            *(char2*)(g_h + (size_t)(r0 + 8) * DH + n0 + col) = c23;
            cnt += (fabsf(fabsf(w0) - THRESH) < MARGIN);
            cnt += (fabsf(fabsf(w1v) - THRESH) < MARGIN);
            cnt += (fabsf(fabsf(w2v) - THRESH) < MARGIN);
            cnt += (fabsf(fabsf(w3) - THRESH) < MARGIN);
        }
    }
    int incl = cnt;
#pragma unroll
    for (int d = 1; d < 32; d <<= 1) {
        int t = __shfl_up_sync(0xFFFFFFFFu, incl, d);
        if (lane >= d) incl += t;
    }
    const int excl = incl - cnt;
    const int tot  = __shfl_sync(0xFFFFFFFFu, incl, 31);
    if (tot) {
        int base = 0;
        if (lane == 0) base = atomicAdd(&g_cnt, tot);
        base = __shfl_sync(0xFFFFFFFFu, base, 0);
        int p = base + excl;
#pragma unroll
        for (int mi = 0; mi < 2; mi++) {
            const int r0 = m0 + wm * 32 + mi * 16 + g;
#pragma unroll
            for (int ni = 0; ni < 5; ni++) {
                const int col = wn * 40 + ni * 8 + tg * 2;
                const float bv0 = b1s[col], bv1 = b1s[col + 1];
                const float vv[4] = { acc[mi][ni][0] + bv0, acc[mi][ni][1] + bv1,
                                      acc[mi][ni][2] + bv0, acc[mi][ni][3] + bv1 };
                const int rr[4] = { r0, r0, r0 + 8, r0 + 8 };
                const int cc[4] = { col, col + 1, col, col + 1 };
#pragma unroll
                for (int e = 0; e < 4; e++) {
                    if (fabsf(fabsf(vv[e]) - THRESH) < MARGIN) {
                        if (p < CAP)
                            g_list[p] = ((uint32_t)rr[e] << 9) | (uint32_t)(n0 + cc[e]);
                        p++;
                    }
                }
            }
        }
    }
}

// ============================================================================
// Correction: exact fp32 recompute of flagged h elements. Warp per entry,
// float4 x loads (MLP 6-7/lane), half2 weights from L2.
// ============================================================================
__global__ __launch_bounds__(256)
void corr_kernel(const float* __restrict__ x, const float* __restrict__ b1) {
    const int lane = threadIdx.x & 31;
    const int wg   = (blockIdx.x * 256 + threadIdx.x) >> 5;
    const int nw   = (gridDim.x * 256) >> 5;
    int total = g_cnt;
    if (total > CAP) total = CAP;

    for (int e = wg; e < total; e += nw) {
        const uint32_t u = g_list[e];
        const int row = (int)(u >> 9);
        const int n   = (int)(u & 511);
        const float4*  xr = (const float4*)(x + (size_t)row * DIN);
        const __half2* wr = (const __half2*)(g_w1h + (size_t)n * DIN);
        float s = 0.0f;
#pragma unroll
        for (int i = 0; i < 6; i++) {            // 6*32 = 192 float4
            const int idx = lane + i * 32;
            float4  v  = xr[idx];
            __half2 wa = wr[idx * 2];
            __half2 wb = wr[idx * 2 + 1];
            float2 fa = __half22float2(wa), fb = __half22float2(wb);
            s += v.x * fa.x + v.y * fa.y + v.z * fb.x + v.w * fb.y;
        }
        if (lane < 4) {                          // remaining 4 float4 (192..195)
            const int idx = 192 + lane;
            float4  v  = xr[idx];
            __half2 wa = wr[idx * 2];
            __half2 wb = wr[idx * 2 + 1];
            float2 fa = __half22float2(wa), fb = __half22float2(wb);
            s += v.x * fa.x + v.y * fa.y + v.z * fb.x + v.w * fb.y;
        }
#pragma unroll
        for (int d = 16; d; d >>= 1)
            s += __shfl_xor_sync(0xFFFFFFFFu, s, d);
        if (lane == 0)
            g_h[(size_t)row * DH + n] = (int8_t)tern_i(s + b1[n]);
    }
}

// ============================================================================
// Head: logits = g_h @ tern(w2)^T + b2 ; log_softmax. 4 threads per row.
// ============================================================================
__global__ __launch_bounds__(256)
void head_kernel(const float* __restrict__ w2,
                 const float* __restrict__ b2,
                 float* __restrict__ out) {
    __shared__ int   q2p[DOUT][DH / 4];
    __shared__ float b2s[DOUT];

    const int tid = threadIdx.x;
    for (int i = tid; i < DOUT * (DH / 4); i += 256) {
        const int o = i / (DH / 4);
        const int w = i % (DH / 4);
        int word = 0;
#pragma unroll
        for (int j = 0; j < 4; j++) {
            int t = tern_i(w2[o * DH + w * 4 + j]);
            word |= (t & 0xFF) << (8 * j);
        }
        q2p[o][w] = word;
    }
    if (tid < DOUT) b2s[tid] = b2[tid];
    __syncthreads();

    const int gidx   = blockIdx.x * 256 + tid;
    const size_t row = (size_t)(gidx >> 2);
    const int q      = gidx & 3;
    const uint4* hp  = (const uint4*)(g_h + row * DH) + q * 5;

    int acc[DOUT];
#pragma unroll
    for (int o = 0; o < DOUT; o++) acc[o] = 0;

#pragma unroll
    for (int c = 0; c < 5; c++) {
        uint4 v = hp[c];
        const int w = q * 20 + c * 4;
#pragma unroll
        for (int o = 0; o < DOUT; o++) {
            acc[o] = __dp4a((int)v.x, q2p[o][w + 0], acc[o]);
            acc[o] = __dp4a((int)v.y, q2p[o][w + 1], acc[o]);
            acc[o] = __dp4a((int)v.z, q2p[o][w + 2], acc[o]);
            acc[o] = __dp4a((int)v.w, q2p[o][w + 3], acc[o]);
        }
    }
#pragma unroll
    for (int o = 0; o < DOUT; o++) {
        acc[o] += __shfl_xor_sync(0xFFFFFFFFu, acc[o], 1);
        acc[o] += __shfl_xor_sync(0xFFFFFFFFu, acc[o], 2);
    }

    if (q == 0) {
        float lg[DOUT];
        float m = -1e30f;
#pragma unroll
        for (int o = 0; o < DOUT; o++) {
            lg[o] = (float)acc[o] + b2s[o];
            m = fmaxf(m, lg[o]);
        }
        float s = 0.0f;
#pragma unroll
        for (int o = 0; o < DOUT; o++) s += expf(lg[o] - m);
        const float lse = m + logf(s);
        float* op = out + row * DOUT;
#pragma unroll
        for (int o = 0; o < DOUT; o++) op[o] = lg[o] - lse;
    }
}

// ============================================================================
extern "C" void kernel_launch(void* const* d_in, const int* in_sizes, int n_in,
                              void* d_out, int out_size) {
    const float* x  = (const float*)d_in[0];
    const float* w1 = (const float*)d_in[1];
    const float* b1 = (const float*)d_in[2];
    const float* w2 = (const float*)d_in[3];
    const float* b2 = (const float*)d_in[4];
    float* out = (float*)d_out;

    cudaFuncSetAttribute(gemm1_hmma,
                         cudaFuncAttributeMaxDynamicSharedMemorySize, SMEM_DYN);

    prep_w1<<<(DH * DIN / 2 + 255) / 256, 256>>>(w1);
    gemm1_hmma<<<dim3(DH / BN, BATCH / BM), 512, SMEM_DYN>>>(x, b1);
    corr_kernel<<<2048, 256>>>(x, b1);
    head_kernel<<<BATCH * 4 / 256, 256>>>(w2, b2, out);
}